// round 9
// baseline (speedup 1.0000x reference)
#include <cuda_runtime.h>
#include <cuda_bf16.h>
#include <math.h>
#include <stdint.h>

#define NTOK 4096
#define DMODEL 512
#define NEXP 8
#define HDIM 2048
#define EHDIM (NEXP * HDIM)   // 16384

// ---------------- device scratch ----------------
// int8 split (hi/lo) operands for gate/up GEMM
__device__ __align__(16) int8_t g_qxh[NTOK * DMODEL];
__device__ __align__(16) int8_t g_qxl[NTOK * DMODEL];
__device__ __align__(16) int8_t g_qgh[EHDIM * DMODEL];   // [EH][D] transposed
__device__ __align__(16) int8_t g_qgl[EHDIM * DMODEL];
__device__ __align__(16) int8_t g_quh[EHDIM * DMODEL];
__device__ __align__(16) int8_t g_qul[EHDIM * DMODEL];
__device__ float g_sx[NTOK];
__device__ float g_swg[EHDIM];
__device__ float g_swu[EHDIM];
// bf16 split for down GEMM (w_down transposed to [D][H])
__device__ __align__(16) unsigned short g_wdh[DMODEL * HDIM];
__device__ __align__(16) unsigned short g_wdl[DMODEL * HDIM];
__device__ __align__(16) float  g_part[2 * NTOK * HDIM];
__device__ int    g_cnt[NEXP];
__device__ double g_esum[NEXP];
__device__ int    g_elist[NEXP * NTOK];   // token | (slot<<16)
__device__ float  g_eprob[NEXP * NTOK];

// ---------------- helpers ----------------
__device__ __forceinline__ uint32_t smem_u32(const void* p) {
    uint32_t a;
    asm("{ .reg .u64 t; cvta.to.shared.u64 t, %1; cvt.u32.u64 %0, t; }"
        : "=r"(a) : "l"(p));
    return a;
}
__device__ __forceinline__ void cp16(uint32_t dst, const void* src) {
    asm volatile("cp.async.cg.shared.global [%0], [%1], 16;" :: "r"(dst), "l"(src));
}
#define CP_COMMIT() asm volatile("cp.async.commit_group;" ::: "memory")
#define CP_WAIT2()  asm volatile("cp.async.wait_group 2;" ::: "memory")
#define CP_WAIT1()  asm volatile("cp.async.wait_group 1;" ::: "memory")
#define CP_WAIT0()  asm volatile("cp.async.wait_group 0;" ::: "memory")

__device__ __forceinline__ void ldm4(uint32_t* r, uint32_t addr) {
    asm volatile("ldmatrix.sync.aligned.m8n8.x4.shared.b16 {%0,%1,%2,%3}, [%4];"
                 : "=r"(r[0]), "=r"(r[1]), "=r"(r[2]), "=r"(r[3]) : "r"(addr));
}

// bf16 MMA (down GEMM)
__device__ __forceinline__ void mma16(float* c, const uint32_t* a, const uint32_t* b) {
    asm volatile(
        "mma.sync.aligned.m16n8k16.row.col.f32.bf16.bf16.f32 "
        "{%0,%1,%2,%3}, {%4,%5,%6,%7}, {%8,%9}, {%0,%1,%2,%3};"
        : "+f"(c[0]), "+f"(c[1]), "+f"(c[2]), "+f"(c[3])
        : "r"(a[0]), "r"(a[1]), "r"(a[2]), "r"(a[3]), "r"(b[0]), "r"(b[1]));
}
// int8 MMA (gate/up GEMM)
__device__ __forceinline__ void imma32(int* c, const uint32_t* a, const uint32_t* b) {
    asm volatile(
        "mma.sync.aligned.m16n8k32.row.col.s32.s8.s8.s32 "
        "{%0,%1,%2,%3}, {%4,%5,%6,%7}, {%8,%9}, {%0,%1,%2,%3};"
        : "+r"(c[0]), "+r"(c[1]), "+r"(c[2]), "+r"(c[3])
        : "r"(a[0]), "r"(a[1]), "r"(a[2]), "r"(a[3]), "r"(b[0]), "r"(b[1]));
}

__device__ __forceinline__ void bsplit(float v, unsigned short& h, unsigned short& l) {
    __nv_bfloat16 hb = __float2bfloat16(v);
    h = __bfloat16_as_ushort(hb);
    float r = v - __bfloat162float(hb);
    l = __bfloat16_as_ushort(__float2bfloat16(r));
}
__device__ __forceinline__ uint32_t pack2(unsigned short a, unsigned short b) {
    return (uint32_t)a | ((uint32_t)b << 16);
}
// quantize one float to (qh, ql) given inv scale; q = qh*128 + ql exactly
__device__ __forceinline__ void qsplit(float v, float inv, int& qh, int& ql) {
    float q = rintf(v * inv);                 // |q| <= 16256
    float qhf = rintf(q * (1.0f / 128.0f));   // |qh| <= 127
    qh = (int)qhf;
    ql = (int)(q - qhf * 128.0f);             // |ql| <= 64
}
__device__ __forceinline__ uint32_t packb4(int a, int b, int c, int d) {
    return (uint32_t)(a & 0xFF) | ((uint32_t)(b & 0xFF) << 8) |
           ((uint32_t)(c & 0xFF) << 16) | ((uint32_t)(d & 0xFF) << 24);
}

// ---------------- x quantization: one warp per token ----------------
__global__ void prep_x_q(const float* __restrict__ x) {
    int gt = blockIdx.x * blockDim.x + threadIdx.x;
    if (gt == 0) {
#pragma unroll
        for (int e = 0; e < NEXP; e++) { g_cnt[e] = 0; g_esum[e] = 0.0; }
    }
    int warp = gt >> 5, lane = gt & 31;
    if (warp >= NTOK) return;
    const float4* xr = reinterpret_cast<const float4*>(x + (size_t)warp * DMODEL) + lane * 4;
    float4 v[4];
    float m = 0.f;
#pragma unroll
    for (int i = 0; i < 4; i++) {
        v[i] = xr[i];
        m = fmaxf(m, fmaxf(fmaxf(fabsf(v[i].x), fabsf(v[i].y)),
                           fmaxf(fabsf(v[i].z), fabsf(v[i].w))));
    }
#pragma unroll
    for (int off = 16; off > 0; off >>= 1)
        m = fmaxf(m, __shfl_xor_sync(0xFFFFFFFFu, m, off));
    float mm = fmaxf(m, 1e-20f);
    float s = mm / 16256.f;
    float inv = 16256.f / mm;
    if (lane == 0) g_sx[warp] = s;

    uint32_t hw[4], lw[4];
#pragma unroll
    for (int i = 0; i < 4; i++) {
        int h0, l0, h1, l1, h2, l2, h3, l3;
        qsplit(v[i].x, inv, h0, l0); qsplit(v[i].y, inv, h1, l1);
        qsplit(v[i].z, inv, h2, l2); qsplit(v[i].w, inv, h3, l3);
        hw[i] = packb4(h0, h1, h2, h3);
        lw[i] = packb4(l0, l1, l2, l3);
    }
    size_t o = (size_t)warp * DMODEL + lane * 16;
    *reinterpret_cast<uint4*>(g_qxh + o) = make_uint4(hw[0], hw[1], hw[2], hw[3]);
    *reinterpret_cast<uint4*>(g_qxl + o) = make_uint4(lw[0], lw[1], lw[2], lw[3]);
}

// ---------------- weight quantization + transpose (gate & up) ----------------
__global__ void prep_wq(const float* __restrict__ wg, const float* __restrict__ wu) {
    __shared__ float mg[8][32], mu[8][32];
    __shared__ float ivg[32], ivu[32];
    __shared__ float tg[32][33], tu[32][33];
    int h0 = blockIdx.x * 32;
    int tx = threadIdx.x, ty = threadIdx.y;   // (32, 8)

    float ag = 0.f, au = 0.f;
    for (int dc = 0; dc < 16; dc++) {
#pragma unroll
        for (int i = 0; i < 4; i++) {
            size_t o = (size_t)(dc * 32 + ty + i * 8) * EHDIM + h0 + tx;
            ag = fmaxf(ag, fabsf(wg[o]));
            au = fmaxf(au, fabsf(wu[o]));
        }
    }
    mg[ty][tx] = ag; mu[ty][tx] = au;
    __syncthreads();
    if (ty == 0) {
        float a = mg[0][tx], b = mu[0][tx];
#pragma unroll
        for (int j = 1; j < 8; j++) { a = fmaxf(a, mg[j][tx]); b = fmaxf(b, mu[j][tx]); }
        a = fmaxf(a, 1e-20f); b = fmaxf(b, 1e-20f);
        g_swg[h0 + tx] = a / 16256.f;  ivg[tx] = 16256.f / a;
        g_swu[h0 + tx] = b / 16256.f;  ivu[tx] = 16256.f / b;
    }
    __syncthreads();

    for (int dc = 0; dc < 16; dc++) {
#pragma unroll
        for (int i = 0; i < 4; i++) {
            size_t o = (size_t)(dc * 32 + ty + i * 8) * EHDIM + h0 + tx;
            tg[ty + i * 8][tx] = wg[o];
            tu[ty + i * 8][tx] = wu[o];
        }
        __syncthreads();
#pragma unroll
        for (int i = 0; i < 4; i++) {
            int hh = ty + i * 8;
            int d = dc * 32 + tx;
            size_t o = (size_t)(h0 + hh) * DMODEL + d;
            int qh, ql;
            qsplit(tg[tx][hh], ivg[hh], qh, ql);
            g_qgh[o] = (int8_t)qh; g_qgl[o] = (int8_t)ql;
            qsplit(tu[tx][hh], ivu[hh], qh, ql);
            g_quh[o] = (int8_t)qh; g_qul[o] = (int8_t)ql;
        }
        __syncthreads();
    }
}

// ---------------- w_down split + transpose (bf16) ----------------
__global__ void prep_wd(const float* __restrict__ wd) {
    __shared__ float t[32][33];
    int db = blockIdx.x * 32, hb = blockIdx.y * 32;
    int tx = threadIdx.x, ty = threadIdx.y;
#pragma unroll
    for (int i = 0; i < 4; i++) {
        t[ty + i * 8][tx] = wd[(size_t)(hb + ty + i * 8) * DMODEL + db + tx];
    }
    __syncthreads();
#pragma unroll
    for (int i = 0; i < 4; i++) {
        size_t o = (size_t)(db + ty + i * 8) * HDIM + hb + tx;
        unsigned short hh, ll;
        bsplit(t[tx][ty + i * 8], hh, ll);
        g_wdh[o] = hh; g_wdl[o] = ll;
    }
}

// ---------------- router: one warp per token ----------------
__global__ void router_kernel(const float* __restrict__ x,
                              const float* __restrict__ w_router) {
    int warp = (blockIdx.x * blockDim.x + threadIdx.x) >> 5;
    int lane = threadIdx.x & 31;
    if (warp >= NTOK) return;
    int n = warp;

    float acc[NEXP];
#pragma unroll
    for (int e = 0; e < NEXP; e++) acc[e] = 0.f;
    const float* xr = x + (size_t)n * DMODEL;
    for (int d = lane; d < DMODEL; d += 32) {
        float xv = xr[d];
        const float* w = w_router + d * NEXP;
#pragma unroll
        for (int e = 0; e < NEXP; e++) acc[e] += xv * w[e];
    }
#pragma unroll
    for (int off = 16; off > 0; off >>= 1)
#pragma unroll
        for (int e = 0; e < NEXP; e++)
            acc[e] += __shfl_xor_sync(0xFFFFFFFFu, acc[e], off);

    if (lane == 0) {
        float mx = acc[0];
#pragma unroll
        for (int e = 1; e < NEXP; e++) mx = fmaxf(mx, acc[e]);
        float s = 0.f, probs[NEXP];
#pragma unroll
        for (int e = 0; e < NEXP; e++) { probs[e] = expf(acc[e] - mx); s += probs[e]; }
        float inv = 1.f / s;
#pragma unroll
        for (int e = 0; e < NEXP; e++) {
            probs[e] *= inv;
            atomicAdd(&g_esum[e], (double)probs[e]);
        }
        int i1 = 0;
#pragma unroll
        for (int e = 1; e < NEXP; e++) if (probs[e] > probs[i1]) i1 = e;
        int i2 = (i1 == 0) ? 1 : 0;
#pragma unroll
        for (int e = 0; e < NEXP; e++)
            if (e != i1 && probs[e] > probs[i2]) i2 = e;

        float p1 = probs[i1], p2 = probs[i2];
        float rn = 1.f / (p1 + p2 + 1e-10f);
        int pos1 = atomicAdd(&g_cnt[i1], 1);
        g_elist[i1 * NTOK + pos1] = n;                // slot 0
        g_eprob[i1 * NTOK + pos1] = p1 * rn;
        int pos2 = atomicAdd(&g_cnt[i2], 1);
        g_elist[i2 * NTOK + pos2] = n | (1 << 16);    // slot 1
        g_eprob[i2 * NTOK + pos2] = p2 * rn;
    }
}

// ---------------- gate/up int8-split IMMA GEMM ----------------
// 512 threads = 16 warps (wm4 x wn4). BM=64 tokens, BN=64 h (dual G,U).
// smem row = [hi 32B(k0-31) | lo 32B | pad 16B] stride 80B.
// 3-stage cp.async, ONE barrier per iteration (prologue 2, wait_group 1).
#define GQS 80
#define GSTG 15360                       // X(5120) + G(5120) + U(5120)
#define GU_X(s) ((s) * GSTG)
#define GU_G(s) ((s) * GSTG + 5120)
#define GU_U(s) ((s) * GSTG + 10240)
#define GU_META (3 * GSTG)               // 46080
#define GU_DYN  (GU_META + 2048)

__global__ __launch_bounds__(512, 1) void gateup_i8() {
    extern __shared__ __align__(16) char smem[];
    uint32_t sb = smem_u32(smem);
    float*  sP   = reinterpret_cast<float*>(smem + GU_META);          // 64
    float*  sSx  = reinterpret_cast<float*>(smem + GU_META + 256);    // 64
    float*  sWg  = reinterpret_cast<float*>(smem + GU_META + 512);    // 64
    float*  sWu  = reinterpret_cast<float*>(smem + GU_META + 768);    // 64
    float** sDst = reinterpret_cast<float**>(smem + GU_META + 1024);  // 64

    const int tid = threadIdx.x;
    const int e = blockIdx.z;
    const int cnt = g_cnt[e];
    const int row0 = blockIdx.x * 64;
    if (row0 >= cnt) return;
    const int h0 = blockIdx.y * 64;

    if (tid < 64) {
        int gr = row0 + tid;
        bool valid = gr < cnt;
        int ent = valid ? g_elist[e * NTOK + gr] : 0;
        int t = ent & 0xFFFF;
        int slot = (ent >> 16) & 1;
        sP[tid] = valid ? g_eprob[e * NTOK + gr] : 0.f;
        sSx[tid] = g_sx[t];
        sDst[tid] = valid ? (g_part + ((size_t)slot * NTOK + t) * HDIM + h0) : (float*)0;
    } else if (tid < 128) {
        sWg[tid - 64] = g_swg[e * HDIM + h0 + (tid - 64)];
    } else if (tid < 192) {
        sWu[tid - 128] = g_swu[e * HDIM + h0 + (tid - 128)];
    }

    // cp.async setup: tid<256 -> X (1 op), tid>=256 -> G + U (2 ops)
    const int q = tid & 3, hilo = q >> 1, seg = q & 1;
    const int r = (tid & 255) >> 2;           // 0..63
    const int8_t* xsrc = 0;
    const int8_t* gsrc = 0;
    const int8_t* usrc = 0;
    uint32_t coff_smem;
    if (tid < 256) {
        int gr = row0 + r;
        int ent = (gr < cnt) ? g_elist[e * NTOK + gr] : 0;
        int t = ent & 0xFFFF;
        xsrc = (hilo ? g_qxl : g_qxh) + (size_t)t * DMODEL + seg * 16;
    } else {
        size_t ro = (size_t)(e * HDIM + h0 + r) * DMODEL + seg * 16;
        gsrc = (hilo ? g_qgl : g_qgh) + ro;
        usrc = (hilo ? g_qul : g_quh) + ro;
    }
    coff_smem = (uint32_t)r * GQS + hilo * 32 + seg * 16;

    // fragment addressing
    const int warp = tid >> 5, lane = tid & 31;
    const int wm = warp & 3, wn = warp >> 2;
    const int grp = lane >> 2, tig = lane & 3;
    const uint32_t aLane = (uint32_t)(((lane & 7) + (lane & 8)) * GQS + ((lane & 16) ? 16 : 0));
    const uint32_t bLane = (uint32_t)((((lane & 7) + ((lane & 16) >> 1)) * GQS) + ((lane & 8) ? 16 : 0));
    const uint32_t aBase = (uint32_t)(wm * 16) * GQS + aLane;
    const uint32_t bBase = (uint32_t)(wn * 16) * GQS + bLane;

    int Ghh[2][4], Gx[2][4], Uhh[2][4], Ux[2][4];
#pragma unroll
    for (int nt = 0; nt < 2; nt++)
#pragma unroll
        for (int k = 0; k < 4; k++) {
            Ghh[nt][k] = 0; Gx[nt][k] = 0; Uhh[nt][k] = 0; Ux[nt][k] = 0;
        }

    // prologue: stages 0,1
#pragma unroll
    for (int c = 0; c < 2; c++) {
        if (tid < 256) {
            cp16(sb + GU_X(c) + coff_smem, xsrc + c * 32);
        } else {
            cp16(sb + GU_G(c) + coff_smem, gsrc + c * 32);
            cp16(sb + GU_U(c) + coff_smem, usrc + c * 32);
        }
        CP_COMMIT();
    }

    const int NCH = DMODEL / 32;   // 16
    for (int c = 0; c < NCH; c++) {
        int s = c % 3;
        CP_WAIT1();
        __syncthreads();
        if (c + 2 < NCH) {
            int s2 = (c + 2) % 3;
            if (tid < 256) {
                cp16(sb + GU_X(s2) + coff_smem, xsrc + (c + 2) * 32);
            } else {
                cp16(sb + GU_G(s2) + coff_smem, gsrc + (size_t)(c + 2) * 32);
                cp16(sb + GU_U(s2) + coff_smem, usrc + (size_t)(c + 2) * 32);
            }
        }
        CP_COMMIT();   // uniform group counting

        uint32_t xb = sb + GU_X(s), gb = sb + GU_G(s), ub = sb + GU_U(s);
        uint32_t ah[4], al[4], gH[4], gL[4], uH[4], uL[4];
        ldm4(ah, xb + aBase);      ldm4(al, xb + aBase + 32);
        ldm4(gH, gb + bBase);      ldm4(gL, gb + bBase + 32);
        ldm4(uH, ub + bBase);      ldm4(uL, ub + bBase + 32);

#pragma unroll
        for (int nt = 0; nt < 2; nt++) {
            imma32(Ghh[nt], ah, gH + nt * 2);
            imma32(Gx[nt],  ah, gL + nt * 2);
            imma32(Gx[nt],  al, gH + nt * 2);
            imma32(Uhh[nt], ah, uH + nt * 2);
            imma32(Ux[nt],  ah, uL + nt * 2);
            imma32(Ux[nt],  al, uH + nt * 2);
        }
    }

    // epilogue: g = sx*sw*(16384*hh + 128*cross); val = p*silu(g)*u
    int r0 = wm * 16 + grp;
    int r1 = r0 + 8;
    float sx0 = sSx[r0], sx1 = sSx[r1];
    float p0 = sP[r0], p1 = sP[r1];
    float* d0 = sDst[r0];
    float* d1 = sDst[r1];
#pragma unroll
    for (int nt = 0; nt < 2; nt++) {
        int co = wn * 16 + nt * 8 + tig * 2;
        float wg0 = sWg[co], wg1 = sWg[co + 1];
        float wu0 = sWu[co], wu1 = sWu[co + 1];
        if (d0) {
            float ga = sx0 * wg0 * (16384.f * (float)Ghh[nt][0] + 128.f * (float)Gx[nt][0]);
            float gb2 = sx0 * wg1 * (16384.f * (float)Ghh[nt][1] + 128.f * (float)Gx[nt][1]);
            float ua = sx0 * wu0 * (16384.f * (float)Uhh[nt][0] + 128.f * (float)Ux[nt][0]);
            float ub2 = sx0 * wu1 * (16384.f * (float)Uhh[nt][1] + 128.f * (float)Ux[nt][1]);
            float2 v;
            v.x = p0 * (ga / (1.f + __expf(-ga))) * ua;
            v.y = p0 * (gb2 / (1.f + __expf(-gb2))) * ub2;
            *reinterpret_cast<float2*>(d0 + co) = v;
        }
        if (d1) {
            float ga = sx1 * wg0 * (16384.f * (float)Ghh[nt][2] + 128.f * (float)Gx[nt][2]);
            float gb2 = sx1 * wg1 * (16384.f * (float)Ghh[nt][3] + 128.f * (float)Gx[nt][3]);
            float ua = sx1 * wu0 * (16384.f * (float)Uhh[nt][2] + 128.f * (float)Ux[nt][2]);
            float ub2 = sx1 * wu1 * (16384.f * (float)Uhh[nt][3] + 128.f * (float)Ux[nt][3]);
            float2 v;
            v.x = p1 * (ga / (1.f + __expf(-ga))) * ua;
            v.y = p1 * (gb2 / (1.f + __expf(-gb2))) * ub2;
            *reinterpret_cast<float2*>(d1 + co) = v;
        }
    }
}

// ---------------- down split-bf16 warp-MMA GEMM ----------------
#define RS 20
#define XSTG 10240          // 128*80
#define WSTG 5120           // 64*80
__global__ __launch_bounds__(512, 1) void down_mma(float* __restrict__ out) {
    __shared__ __align__(16) uint32_t As[3][128 * RS];
    __shared__ __align__(16) uint32_t Bs[3][64 * RS];

    const int tid = threadIdx.x;
    const int row0 = blockIdx.x * 128;
    const int c0 = blockIdx.y * 64;

    const int ar = tid >> 2, ac4 = tid & 3;
    const float4* asrc0 =
        reinterpret_cast<const float4*>(g_part + (size_t)(row0 + ar) * HDIM) + ac4;
    const float4* asrc1 =
        reinterpret_cast<const float4*>(g_part + (size_t)NTOK * HDIM +
                                        (size_t)(row0 + ar) * HDIM) + ac4;
    uint32_t adh0 = smem_u32(&As[0][ar * RS + ac4 * 2]);

    const int q = tid & 3, hilo = q >> 1, seg = q & 1;
    const int brow = (tid & 255) >> 2;
    const unsigned short* bsrc =
        (hilo ? g_wdl : g_wdh) + (size_t)(c0 + brow) * HDIM + seg * 8;
    uint32_t bdst0 = smem_u32(&Bs[0][0]) + (uint32_t)brow * 80 + hilo * 32 + seg * 16;

    const int warp = tid >> 5, lane = tid & 31;
    const int wm = warp & 3, wn = warp >> 2;
    const int grp = lane >> 2, tig = lane & 3;
    const uint32_t aLane = (uint32_t)(((lane & 7) + (lane & 8)) * 80 + ((lane & 16) ? 16 : 0));
    const uint32_t bLane = (uint32_t)((((lane & 7) + ((lane & 16) >> 1)) * 80) + ((lane & 8) ? 16 : 0));
    uint32_t aFB[2][2];
#pragma unroll
    for (int mt = 0; mt < 2; mt++)
#pragma unroll
        for (int hl = 0; hl < 2; hl++)
            aFB[mt][hl] = smem_u32(&As[0][0]) +
                          (uint32_t)((wm * 32 + mt * 16) * 80 + hl * 32) + aLane;
    uint32_t bFB[2] = { smem_u32(&Bs[0][0]) + (uint32_t)(wn * 16 * 80) + bLane,
                        smem_u32(&Bs[0][0]) + (uint32_t)(wn * 16 * 80 + 32) + bLane };

    float acc[2][2][4];
#pragma unroll
    for (int mt = 0; mt < 2; mt++)
#pragma unroll
        for (int nt = 0; nt < 2; nt++)
#pragma unroll
            for (int k = 0; k < 4; k++) acc[mt][nt][k] = 0.f;

    float4 rA0 = asrc0[0], rA1 = asrc1[0];

#pragma unroll
    for (int c = 0; c < 3; c++) {
        if (tid < 256) cp16(bdst0 + c * (64 * 80), bsrc + (size_t)c * 16);  // FIX: k-advance along row
        CP_COMMIT();
    }

    const int NCH = HDIM / 16;   // 128
    for (int c = 0; c < NCH; c++) {
        int s = c % 3;
        {
            float s0 = rA0.x + rA1.x, s1 = rA0.y + rA1.y;
            float s2 = rA0.z + rA1.z, s3 = rA0.w + rA1.w;
            unsigned short h0, h1, h2, h3, l0, l1, l2, l3;
            bsplit(s0, h0, l0); bsplit(s1, h1, l1);
            bsplit(s2, h2, l2); bsplit(s3, h3, l3);
            uint32_t hw0 = pack2(h0, h1), hw1 = pack2(h2, h3);
            uint32_t lw0 = pack2(l0, l1), lw1 = pack2(l2, l3);
            uint32_t dst = adh0 + s * XSTG;
            asm volatile("st.shared.v2.b32 [%0], {%1,%2};"
                         :: "r"(dst), "r"(hw0), "r"(hw1) : "memory");
            asm volatile("st.shared.v2.b32 [%0], {%1,%2};"
                         :: "r"(dst + 32), "r"(lw0), "r"(lw1) : "memory");
        }
        if (c + 1 < NCH) { rA0 = asrc0[(c + 1) * 4]; rA1 = asrc1[(c + 1) * 4]; }
        if (c < NCH - 2) CP_WAIT2(); else if (c == NCH - 2) CP_WAIT1(); else CP_WAIT0();
        __syncthreads();

        uint32_t ah[2][4], al[2][4];
        ldm4(ah[0], aFB[0][0] + s * XSTG); ldm4(al[0], aFB[0][1] + s * XSTG);
        ldm4(ah[1], aFB[1][0] + s * XSTG); ldm4(al[1], aFB[1][1] + s * XSTG);
        uint32_t bH[4], bL[4];
        ldm4(bH, bFB[0] + s * WSTG); ldm4(bL, bFB[1] + s * WSTG);

#pragma unroll
        for (int mt = 0; mt < 2; mt++)
#pragma unroll
            for (int nt = 0; nt < 2; nt++) {
                mma16(acc[mt][nt], ah[mt], bH + nt * 2);
                mma16(acc[mt][nt], ah[mt], bL + nt * 2);
                mma16(acc[mt][nt], al[mt], bH + nt * 2);
            }
        __syncthreads();

        if (c + 3 < NCH) {
            if (tid < 256)
                cp16(bdst0 + s * (64 * 80), bsrc + (size_t)(c + 3) * 16);  // FIX
            CP_COMMIT();
        }
    }

#pragma unroll
    for (int mt = 0; mt < 2; mt++) {
        int r0 = row0 + wm * 32 + mt * 16 + grp;
        int r1 = r0 + 8;
#pragma unroll
        for (int nt = 0; nt < 2; nt++) {
            int coff = c0 + wn * 16 + nt * 8 + tig * 2;
            float2 v0 = make_float2(acc[mt][nt][0], acc[mt][nt][1]);
            float2 v1 = make_float2(acc[mt][nt][2], acc[mt][nt][3]);
            *reinterpret_cast<float2*>(out + (size_t)r0 * DMODEL + coff) = v0;
            *reinterpret_cast<float2*>(out + (size_t)r1 * DMODEL + coff) = v1;
        }
    }
}

// ---------------- load-balancing loss (fp64) ----------------
__global__ void lbloss_kernel(float* __restrict__ out_scalar) {
    if (threadIdx.x == 0 && blockIdx.x == 0) {
        double lb = 0.0;
#pragma unroll
        for (int e = 0; e < NEXP; e++) {
            double m = g_esum[e] / (double)NTOK;
            lb += m * log(m * (double)NEXP + 1e-10);
        }
        out_scalar[0] = (float)((double)NEXP * lb);
    }
}

// ---------------- launch ----------------
extern "C" void kernel_launch(void* const* d_in, const int* in_sizes, int n_in,
                              void* d_out, int out_size) {
    const float* x        = (const float*)d_in[0];
    const float* w_router = (const float*)d_in[1];
    const float* w_gate   = (const float*)d_in[2];
    const float* w_up     = (const float*)d_in[3];
    const float* w_down   = (const float*)d_in[4];
    float* out = (float*)d_out;

    cudaFuncSetAttribute(gateup_i8, cudaFuncAttributeMaxDynamicSharedMemorySize, GU_DYN);

    prep_x_q<<<NTOK / 8, 256>>>(x);                         // also zeroes cnt/esum
    prep_wq<<<EHDIM / 32, dim3(32, 8)>>>(w_gate, w_up);
    router_kernel<<<NTOK / 8, 256>>>(x, w_router);
    gateup_i8<<<dim3(NTOK / 64, HDIM / 64, NEXP), 512, GU_DYN>>>();
    prep_wd<<<dim3(DMODEL / 32, HDIM / 32), dim3(32, 8)>>>(w_down);
    down_mma<<<dim3(NTOK / 128, DMODEL / 64), 512>>>(out);
    lbloss_kernel<<<1, 32>>>(out + (out_size - 1));
}

// round 10
// speedup vs baseline: 1.0168x; 1.0168x over previous
#include <cuda_runtime.h>
#include <cuda_bf16.h>
#include <math.h>
#include <stdint.h>

#define NTOK 4096
#define DMODEL 512
#define NEXP 8
#define HDIM 2048
#define EHDIM (NEXP * HDIM)   // 16384

// ---------------- device scratch ----------------
__device__ __align__(16) unsigned short g_xh[NTOK * DMODEL];
__device__ __align__(16) unsigned short g_xl[NTOK * DMODEL];
__device__ __align__(16) unsigned short g_wgh[EHDIM * DMODEL];   // [EH][D] transposed
__device__ __align__(16) unsigned short g_wgl[EHDIM * DMODEL];
__device__ __align__(16) unsigned short g_wuh[EHDIM * DMODEL];
__device__ __align__(16) unsigned short g_wul[EHDIM * DMODEL];
__device__ __align__(16) unsigned short g_wdh[DMODEL * HDIM];    // [D][H] transposed
__device__ __align__(16) unsigned short g_wdl[DMODEL * HDIM];
__device__ __align__(16) float  g_part[2 * NTOK * HDIM];
__device__ int    g_cnt[NEXP];
__device__ double g_esum[NEXP];
__device__ int    g_elist[NEXP * NTOK];   // token | (slot<<16)
__device__ float  g_eprob[NEXP * NTOK];

// ---------------- helpers ----------------
__device__ __forceinline__ uint32_t smem_u32(const void* p) {
    uint32_t a;
    asm("{ .reg .u64 t; cvta.to.shared.u64 t, %1; cvt.u32.u64 %0, t; }"
        : "=r"(a) : "l"(p));
    return a;
}
__device__ __forceinline__ void cp16(uint32_t dst, const void* src) {
    asm volatile("cp.async.cg.shared.global [%0], [%1], 16;" :: "r"(dst), "l"(src));
}
#define CP_COMMIT() asm volatile("cp.async.commit_group;" ::: "memory")
#define CP_WAIT2()  asm volatile("cp.async.wait_group 2;" ::: "memory")
#define CP_WAIT1()  asm volatile("cp.async.wait_group 1;" ::: "memory")
#define CP_WAIT0()  asm volatile("cp.async.wait_group 0;" ::: "memory")

__device__ __forceinline__ void ldm4(uint32_t* r, uint32_t addr) {
    asm volatile("ldmatrix.sync.aligned.m8n8.x4.shared.b16 {%0,%1,%2,%3}, [%4];"
                 : "=r"(r[0]), "=r"(r[1]), "=r"(r[2]), "=r"(r[3]) : "r"(addr));
}

// m16n8k16 bf16 MMA (sm_80 baseline PTX -> tensor pipe)
__device__ __forceinline__ void mma16(float* c, const uint32_t* a, const uint32_t* b) {
    asm volatile(
        "mma.sync.aligned.m16n8k16.row.col.f32.bf16.bf16.f32 "
        "{%0,%1,%2,%3}, {%4,%5,%6,%7}, {%8,%9}, {%0,%1,%2,%3};"
        : "+f"(c[0]), "+f"(c[1]), "+f"(c[2]), "+f"(c[3])
        : "r"(a[0]), "r"(a[1]), "r"(a[2]), "r"(a[3]), "r"(b[0]), "r"(b[1]));
}

__device__ __forceinline__ void bsplit(float v, unsigned short& h, unsigned short& l) {
    __nv_bfloat16 hb = __float2bfloat16(v);
    h = __bfloat16_as_ushort(hb);
    float r = v - __bfloat162float(hb);
    l = __bfloat16_as_ushort(__float2bfloat16(r));
}
__device__ __forceinline__ uint32_t pack2(unsigned short a, unsigned short b) {
    return (uint32_t)a | ((uint32_t)b << 16);
}

// ---------------- prep kernels ----------------
__global__ void prep_xc(const float* __restrict__ x) {
    int i = blockIdx.x * blockDim.x + threadIdx.x;
    if (i == 0) {
#pragma unroll
        for (int e = 0; e < NEXP; e++) { g_cnt[e] = 0; g_esum[e] = 0.0; }
    }
    float4 v = reinterpret_cast<const float4*>(x)[i];
    unsigned short h0, h1, h2, h3, l0, l1, l2, l3;
    bsplit(v.x, h0, l0); bsplit(v.y, h1, l1);
    bsplit(v.z, h2, l2); bsplit(v.w, h3, l3);
    reinterpret_cast<ushort4*>(g_xh)[i] = make_ushort4(h0, h1, h2, h3);
    reinterpret_cast<ushort4*>(g_xl)[i] = make_ushort4(l0, l1, l2, l3);
}

__global__ void prep_wgu(const float* __restrict__ wg, const float* __restrict__ wu) {
    __shared__ float tg[32][33], tu[32][33];
    int hb = blockIdx.x * 32, db = blockIdx.y * 32;
    int tx = threadIdx.x, ty = threadIdx.y;   // (32, 8)
#pragma unroll
    for (int i = 0; i < 4; i++) {
        int d = db + ty + i * 8;
        tg[ty + i * 8][tx] = wg[(size_t)d * EHDIM + hb + tx];
        tu[ty + i * 8][tx] = wu[(size_t)d * EHDIM + hb + tx];
    }
    __syncthreads();
#pragma unroll
    for (int i = 0; i < 4; i++) {
        int h = hb + ty + i * 8;
        size_t o = (size_t)h * DMODEL + db + tx;
        unsigned short hh, ll;
        bsplit(tg[tx][ty + i * 8], hh, ll);
        g_wgh[o] = hh; g_wgl[o] = ll;
        bsplit(tu[tx][ty + i * 8], hh, ll);
        g_wuh[o] = hh; g_wul[o] = ll;
    }
}

__global__ void prep_wd(const float* __restrict__ wd) {
    __shared__ float t[32][33];
    int db = blockIdx.x * 32, hb = blockIdx.y * 32;
    int tx = threadIdx.x, ty = threadIdx.y;
#pragma unroll
    for (int i = 0; i < 4; i++) {
        t[ty + i * 8][tx] = wd[(size_t)(hb + ty + i * 8) * DMODEL + db + tx];
    }
    __syncthreads();
#pragma unroll
    for (int i = 0; i < 4; i++) {
        size_t o = (size_t)(db + ty + i * 8) * HDIM + hb + tx;
        unsigned short hh, ll;
        bsplit(t[tx][ty + i * 8], hh, ll);
        g_wdh[o] = hh; g_wdl[o] = ll;
    }
}

// ---------------- router: one warp per token ----------------
__global__ void router_kernel(const float* __restrict__ x,
                              const float* __restrict__ w_router) {
    int warp = (blockIdx.x * blockDim.x + threadIdx.x) >> 5;
    int lane = threadIdx.x & 31;
    if (warp >= NTOK) return;
    int n = warp;

    float acc[NEXP];
#pragma unroll
    for (int e = 0; e < NEXP; e++) acc[e] = 0.f;
    const float* xr = x + (size_t)n * DMODEL;
    for (int d = lane; d < DMODEL; d += 32) {
        float xv = xr[d];
        const float* w = w_router + d * NEXP;
#pragma unroll
        for (int e = 0; e < NEXP; e++) acc[e] += xv * w[e];
    }
#pragma unroll
    for (int off = 16; off > 0; off >>= 1)
#pragma unroll
        for (int e = 0; e < NEXP; e++)
            acc[e] += __shfl_xor_sync(0xFFFFFFFFu, acc[e], off);

    if (lane == 0) {
        float mx = acc[0];
#pragma unroll
        for (int e = 1; e < NEXP; e++) mx = fmaxf(mx, acc[e]);
        float s = 0.f, probs[NEXP];
#pragma unroll
        for (int e = 0; e < NEXP; e++) { probs[e] = expf(acc[e] - mx); s += probs[e]; }
        float inv = 1.f / s;
#pragma unroll
        for (int e = 0; e < NEXP; e++) {
            probs[e] *= inv;
            atomicAdd(&g_esum[e], (double)probs[e]);
        }
        int i1 = 0;
#pragma unroll
        for (int e = 1; e < NEXP; e++) if (probs[e] > probs[i1]) i1 = e;
        int i2 = (i1 == 0) ? 1 : 0;
#pragma unroll
        for (int e = 0; e < NEXP; e++)
            if (e != i1 && probs[e] > probs[i2]) i2 = e;

        float p1 = probs[i1], p2 = probs[i2];
        float rn = 1.f / (p1 + p2 + 1e-10f);
        int pos1 = atomicAdd(&g_cnt[i1], 1);
        g_elist[i1 * NTOK + pos1] = n;                // slot 0
        g_eprob[i1 * NTOK + pos1] = p1 * rn;
        int pos2 = atomicAdd(&g_cnt[i2], 1);
        g_elist[i2 * NTOK + pos2] = n | (1 << 16);    // slot 1
        g_eprob[i2 * NTOK + pos2] = p2 * rn;
    }
}

// ---------------- gate/up split-bf16 GEMM, i8-style skeleton ----------------
// 512 threads = 16 warps (wm4 x wn4). BM=64 tokens, BN=64 h (dual G,U).
// smem row = [hi 32B (k16) | lo 32B | pad 16B] stride 80B.
// 3-stage cp.async, ONE barrier per iteration (prologue 2, wait_group 1).
#define GQS 80
#define GSTG 15360                       // X(5120) + G(5120) + U(5120)
#define GU_X(s) ((s) * GSTG)
#define GU_G(s) ((s) * GSTG + 5120)
#define GU_U(s) ((s) * GSTG + 10240)
#define GU_META (3 * GSTG)               // 46080
#define GU_DYN  (GU_META + 1024)

__global__ __launch_bounds__(512, 2) void gateup_bf16() {
    extern __shared__ __align__(16) char smem[];
    uint32_t sb = smem_u32(smem);
    float*  sP   = reinterpret_cast<float*>(smem + GU_META);          // 64 floats
    float** sDst = reinterpret_cast<float**>(smem + GU_META + 256);   // 64 ptrs

    const int tid = threadIdx.x;
    const int e = blockIdx.z;
    const int cnt = g_cnt[e];
    const int row0 = blockIdx.x * 64;
    if (row0 >= cnt) return;
    const int h0 = blockIdx.y * 64;

    if (tid < 64) {
        int gr = row0 + tid;
        bool valid = gr < cnt;
        int ent = valid ? g_elist[e * NTOK + gr] : 0;
        int t = ent & 0xFFFF;
        int slot = (ent >> 16) & 1;
        sP[tid] = valid ? g_eprob[e * NTOK + gr] : 0.f;
        sDst[tid] = valid ? (g_part + ((size_t)slot * NTOK + t) * HDIM + h0) : (float*)0;
    }

    // cp.async setup: tid<256 -> X (1 op), tid>=256 -> G + U (2 ops)
    const int q = tid & 3, hilo = q >> 1, seg = q & 1;
    const int r = (tid & 255) >> 2;           // 0..63
    const unsigned short* xsrc = 0;
    const unsigned short* gsrc = 0;
    const unsigned short* usrc = 0;
    if (tid < 256) {
        int gr = row0 + r;
        int ent = (gr < cnt) ? g_elist[e * NTOK + gr] : 0;
        int t = ent & 0xFFFF;
        xsrc = (hilo ? g_xl : g_xh) + (size_t)t * DMODEL + seg * 8;
    } else {
        size_t ro = (size_t)(e * HDIM + h0 + r) * DMODEL + seg * 8;
        gsrc = (hilo ? g_wgl : g_wgh) + ro;
        usrc = (hilo ? g_wul : g_wuh) + ro;
    }
    const uint32_t coff = (uint32_t)r * GQS + hilo * 32 + seg * 16;

    // fragment addressing (k16 per iter, verified R6 mapping)
    const int warp = tid >> 5, lane = tid & 31;
    const int wm = warp & 3, wn = warp >> 2;
    const int grp = lane >> 2, tig = lane & 3;
    const uint32_t aLane = (uint32_t)(((lane & 7) + (lane & 8)) * GQS + ((lane & 16) ? 16 : 0));
    const uint32_t bLane = (uint32_t)((((lane & 7) + ((lane & 16) >> 1)) * GQS) + ((lane & 8) ? 16 : 0));
    const uint32_t aBase = (uint32_t)(wm * 16) * GQS + aLane;
    const uint32_t bBase = (uint32_t)(wn * 16) * GQS + bLane;

    float accG[2][4], accU[2][4];
#pragma unroll
    for (int nt = 0; nt < 2; nt++)
#pragma unroll
        for (int k = 0; k < 4; k++) { accG[nt][k] = 0.f; accU[nt][k] = 0.f; }

    // prologue: stages 0,1  (chunk = 16 K elems = 32B per row-half)
#pragma unroll
    for (int c = 0; c < 2; c++) {
        if (tid < 256) {
            cp16(sb + GU_X(c) + coff, xsrc + c * 16);
        } else {
            cp16(sb + GU_G(c) + coff, gsrc + c * 16);
            cp16(sb + GU_U(c) + coff, usrc + c * 16);
        }
        CP_COMMIT();
    }

    const int NCH = DMODEL / 16;   // 32
    for (int c = 0; c < NCH; c++) {
        int s = c % 3;
        CP_WAIT1();
        __syncthreads();
        if (c + 2 < NCH) {
            int s2 = (c + 2) % 3;
            if (tid < 256) {
                cp16(sb + GU_X(s2) + coff, xsrc + (c + 2) * 16);
            } else {
                cp16(sb + GU_G(s2) + coff, gsrc + (size_t)(c + 2) * 16);
                cp16(sb + GU_U(s2) + coff, usrc + (size_t)(c + 2) * 16);
            }
        }
        CP_COMMIT();   // uniform group counting

        uint32_t xb = sb + GU_X(s), gb = sb + GU_G(s), ub = sb + GU_U(s);
        uint32_t ah[4], al[4], gH[4], gL[4], uH[4], uL[4];
        ldm4(ah, xb + aBase);      ldm4(al, xb + aBase + 32);
        ldm4(gH, gb + bBase);      ldm4(gL, gb + bBase + 32);
        ldm4(uH, ub + bBase);      ldm4(uL, ub + bBase + 32);

#pragma unroll
        for (int nt = 0; nt < 2; nt++) {
            mma16(accG[nt], ah, gH + nt * 2);
            mma16(accU[nt], ah, uH + nt * 2);
            mma16(accG[nt], ah, gL + nt * 2);
            mma16(accU[nt], ah, uL + nt * 2);
            mma16(accG[nt], al, gH + nt * 2);
            mma16(accU[nt], al, uH + nt * 2);
        }
    }

    // epilogue: p * silu(g) * u  (row/col mapping verified in R9)
    int r0 = wm * 16 + grp;
    int r1 = r0 + 8;
    float p0 = sP[r0], p1 = sP[r1];
    float* d0 = sDst[r0];
    float* d1 = sDst[r1];
#pragma unroll
    for (int nt = 0; nt < 2; nt++) {
        int co = wn * 16 + nt * 8 + tig * 2;
        if (d0) {
            float g0 = accG[nt][0], u0 = accU[nt][0];
            float g1 = accG[nt][1], u1 = accU[nt][1];
            float2 v;
            v.x = p0 * (g0 / (1.f + __expf(-g0))) * u0;
            v.y = p0 * (g1 / (1.f + __expf(-g1))) * u1;
            *reinterpret_cast<float2*>(d0 + co) = v;
        }
        if (d1) {
            float g2 = accG[nt][2], u2 = accU[nt][2];
            float g3 = accG[nt][3], u3 = accU[nt][3];
            float2 v;
            v.x = p1 * (g2 / (1.f + __expf(-g2))) * u2;
            v.y = p1 * (g3 / (1.f + __expf(-g3))) * u3;
            *reinterpret_cast<float2*>(d1 + co) = v;
        }
    }
}

// ---------------- down split-bf16 warp-MMA GEMM (R9 verified) ----------------
#define RS 20
#define XSTG 10240          // 128*80
#define WSTG 5120           // 64*80
__global__ __launch_bounds__(512, 1) void down_mma(float* __restrict__ out) {
    __shared__ __align__(16) uint32_t As[3][128 * RS];
    __shared__ __align__(16) uint32_t Bs[3][64 * RS];

    const int tid = threadIdx.x;
    const int row0 = blockIdx.x * 128;
    const int c0 = blockIdx.y * 64;

    const int ar = tid >> 2, ac4 = tid & 3;
    const float4* asrc0 =
        reinterpret_cast<const float4*>(g_part + (size_t)(row0 + ar) * HDIM) + ac4;
    const float4* asrc1 =
        reinterpret_cast<const float4*>(g_part + (size_t)NTOK * HDIM +
                                        (size_t)(row0 + ar) * HDIM) + ac4;
    uint32_t adh0 = smem_u32(&As[0][ar * RS + ac4 * 2]);

    const int q = tid & 3, hilo = q >> 1, seg = q & 1;
    const int brow = (tid & 255) >> 2;
    const unsigned short* bsrc =
        (hilo ? g_wdl : g_wdh) + (size_t)(c0 + brow) * HDIM + seg * 8;
    uint32_t bdst0 = smem_u32(&Bs[0][0]) + (uint32_t)brow * 80 + hilo * 32 + seg * 16;

    const int warp = tid >> 5, lane = tid & 31;
    const int wm = warp & 3, wn = warp >> 2;
    const int grp = lane >> 2, tig = lane & 3;
    const uint32_t aLane = (uint32_t)(((lane & 7) + (lane & 8)) * 80 + ((lane & 16) ? 16 : 0));
    const uint32_t bLane = (uint32_t)((((lane & 7) + ((lane & 16) >> 1)) * 80) + ((lane & 8) ? 16 : 0));
    uint32_t aFB[2][2];
#pragma unroll
    for (int mt = 0; mt < 2; mt++)
#pragma unroll
        for (int hl = 0; hl < 2; hl++)
            aFB[mt][hl] = smem_u32(&As[0][0]) +
                          (uint32_t)((wm * 32 + mt * 16) * 80 + hl * 32) + aLane;
    uint32_t bFB[2] = { smem_u32(&Bs[0][0]) + (uint32_t)(wn * 16 * 80) + bLane,
                        smem_u32(&Bs[0][0]) + (uint32_t)(wn * 16 * 80 + 32) + bLane };

    float acc[2][2][4];
#pragma unroll
    for (int mt = 0; mt < 2; mt++)
#pragma unroll
        for (int nt = 0; nt < 2; nt++)
#pragma unroll
            for (int k = 0; k < 4; k++) acc[mt][nt][k] = 0.f;

    float4 rA0 = asrc0[0], rA1 = asrc1[0];

#pragma unroll
    for (int c = 0; c < 3; c++) {
        if (tid < 256) cp16(bdst0 + c * (64 * 80), bsrc + (size_t)c * 16);
        CP_COMMIT();
    }

    const int NCH = HDIM / 16;   // 128
    for (int c = 0; c < NCH; c++) {
        int s = c % 3;
        {
            float s0 = rA0.x + rA1.x, s1 = rA0.y + rA1.y;
            float s2 = rA0.z + rA1.z, s3 = rA0.w + rA1.w;
            unsigned short h0, h1, h2, h3, l0, l1, l2, l3;
            bsplit(s0, h0, l0); bsplit(s1, h1, l1);
            bsplit(s2, h2, l2); bsplit(s3, h3, l3);
            uint32_t hw0 = pack2(h0, h1), hw1 = pack2(h2, h3);
            uint32_t lw0 = pack2(l0, l1), lw1 = pack2(l2, l3);
            uint32_t dst = adh0 + s * XSTG;
            asm volatile("st.shared.v2.b32 [%0], {%1,%2};"
                         :: "r"(dst), "r"(hw0), "r"(hw1) : "memory");
            asm volatile("st.shared.v2.b32 [%0], {%1,%2};"
                         :: "r"(dst + 32), "r"(lw0), "r"(lw1) : "memory");
        }
        if (c + 1 < NCH) { rA0 = asrc0[(c + 1) * 4]; rA1 = asrc1[(c + 1) * 4]; }
        if (c < NCH - 2) CP_WAIT2(); else if (c == NCH - 2) CP_WAIT1(); else CP_WAIT0();
        __syncthreads();

        uint32_t ah[2][4], al[2][4];
        ldm4(ah[0], aFB[0][0] + s * XSTG); ldm4(al[0], aFB[0][1] + s * XSTG);
        ldm4(ah[1], aFB[1][0] + s * XSTG); ldm4(al[1], aFB[1][1] + s * XSTG);
        uint32_t bH[4], bL[4];
        ldm4(bH, bFB[0] + s * WSTG); ldm4(bL, bFB[1] + s * WSTG);

#pragma unroll
        for (int mt = 0; mt < 2; mt++)
#pragma unroll
            for (int nt = 0; nt < 2; nt++) {
                mma16(acc[mt][nt], ah[mt], bH + nt * 2);
                mma16(acc[mt][nt], ah[mt], bL + nt * 2);
                mma16(acc[mt][nt], al[mt], bH + nt * 2);
            }
        __syncthreads();

        if (c + 3 < NCH) {
            if (tid < 256)
                cp16(bdst0 + s * (64 * 80), bsrc + (size_t)(c + 3) * 16);
            CP_COMMIT();
        }
    }

#pragma unroll
    for (int mt = 0; mt < 2; mt++) {
        int r0 = row0 + wm * 32 + mt * 16 + grp;
        int r1 = r0 + 8;
#pragma unroll
        for (int nt = 0; nt < 2; nt++) {
            int coff = c0 + wn * 16 + nt * 8 + tig * 2;
            float2 v0 = make_float2(acc[mt][nt][0], acc[mt][nt][1]);
            float2 v1 = make_float2(acc[mt][nt][2], acc[mt][nt][3]);
            *reinterpret_cast<float2*>(out + (size_t)r0 * DMODEL + coff) = v0;
            *reinterpret_cast<float2*>(out + (size_t)r1 * DMODEL + coff) = v1;
        }
    }
}

// ---------------- load-balancing loss (fp64) ----------------
__global__ void lbloss_kernel(float* __restrict__ out_scalar) {
    if (threadIdx.x == 0 && blockIdx.x == 0) {
        double lb = 0.0;
#pragma unroll
        for (int e = 0; e < NEXP; e++) {
            double m = g_esum[e] / (double)NTOK;
            lb += m * log(m * (double)NEXP + 1e-10);
        }
        out_scalar[0] = (float)((double)NEXP * lb);
    }
}

// ---------------- launch ----------------
extern "C" void kernel_launch(void* const* d_in, const int* in_sizes, int n_in,
                              void* d_out, int out_size) {
    const float* x        = (const float*)d_in[0];
    const float* w_router = (const float*)d_in[1];
    const float* w_gate   = (const float*)d_in[2];
    const float* w_up     = (const float*)d_in[3];
    const float* w_down   = (const float*)d_in[4];
    float* out = (float*)d_out;

    cudaFuncSetAttribute(gateup_bf16, cudaFuncAttributeMaxDynamicSharedMemorySize, GU_DYN);

    prep_xc<<<(NTOK * DMODEL / 4) / 256, 256>>>(x);             // also zeroes cnt/esum
    prep_wgu<<<dim3(EHDIM / 32, DMODEL / 32), dim3(32, 8)>>>(w_gate, w_up);
    router_kernel<<<NTOK / 8, 256>>>(x, w_router);
    gateup_bf16<<<dim3(NTOK / 64, HDIM / 64, NEXP), 512, GU_DYN>>>();
    prep_wd<<<dim3(DMODEL / 32, HDIM / 32), dim3(32, 8)>>>(w_down);
    down_mma<<<dim3(NTOK / 128, DMODEL / 64), 512>>>(out);
    lbloss_kernel<<<1, 32>>>(out + (out_size - 1));
}

// round 11
// speedup vs baseline: 1.8876x; 1.8565x over previous
#include <cuda_runtime.h>
#include <cuda_bf16.h>
#include <math.h>
#include <stdint.h>

#define NTOK 4096
#define DMODEL 512
#define NEXP 8
#define HDIM 2048
#define EHDIM (NEXP * HDIM)   // 16384

// ---------------- device scratch ----------------
__device__ __align__(16) unsigned short g_xh[NTOK * DMODEL];
__device__ __align__(16) unsigned short g_xl[NTOK * DMODEL];
__device__ __align__(16) unsigned short g_wgh[EHDIM * DMODEL];   // [EH][D] transposed
__device__ __align__(16) unsigned short g_wgl[EHDIM * DMODEL];
__device__ __align__(16) unsigned short g_wuh[EHDIM * DMODEL];
__device__ __align__(16) unsigned short g_wul[EHDIM * DMODEL];
__device__ __align__(16) unsigned short g_wdh[DMODEL * HDIM];    // [D][H] transposed
__device__ __align__(16) unsigned short g_wdl[DMODEL * HDIM];
__device__ __align__(16) float  g_part[2 * NTOK * HDIM];
__device__ __align__(16) unsigned short g_ah[NTOK * HDIM];       // summed combined, split
__device__ __align__(16) unsigned short g_al[NTOK * HDIM];
__device__ int    g_cnt[NEXP];
__device__ double g_esum[NEXP];
__device__ int    g_elist[NEXP * NTOK];   // token | (slot<<16)
__device__ float  g_eprob[NEXP * NTOK];

// ---------------- helpers ----------------
__device__ __forceinline__ uint32_t smem_u32(const void* p) {
    uint32_t a;
    asm("{ .reg .u64 t; cvta.to.shared.u64 t, %1; cvt.u32.u64 %0, t; }"
        : "=r"(a) : "l"(p));
    return a;
}
__device__ __forceinline__ void cp16(uint32_t dst, const void* src) {
    asm volatile("cp.async.cg.shared.global [%0], [%1], 16;" :: "r"(dst), "l"(src));
}
#define CP_COMMIT() asm volatile("cp.async.commit_group;" ::: "memory")
#define CP_WAIT1()  asm volatile("cp.async.wait_group 1;" ::: "memory")

__device__ __forceinline__ void ldm4(uint32_t* r, uint32_t addr) {
    asm volatile("ldmatrix.sync.aligned.m8n8.x4.shared.b16 {%0,%1,%2,%3}, [%4];"
                 : "=r"(r[0]), "=r"(r[1]), "=r"(r[2]), "=r"(r[3]) : "r"(addr));
}

// m16n8k16 bf16 MMA (sm_80 baseline PTX -> tensor pipe)
__device__ __forceinline__ void mma16(float* c, const uint32_t* a, const uint32_t* b) {
    asm volatile(
        "mma.sync.aligned.m16n8k16.row.col.f32.bf16.bf16.f32 "
        "{%0,%1,%2,%3}, {%4,%5,%6,%7}, {%8,%9}, {%0,%1,%2,%3};"
        : "+f"(c[0]), "+f"(c[1]), "+f"(c[2]), "+f"(c[3])
        : "r"(a[0]), "r"(a[1]), "r"(a[2]), "r"(a[3]), "r"(b[0]), "r"(b[1]));
}

__device__ __forceinline__ void bsplit(float v, unsigned short& h, unsigned short& l) {
    __nv_bfloat16 hb = __float2bfloat16(v);
    h = __bfloat16_as_ushort(hb);
    float r = v - __bfloat162float(hb);
    l = __bfloat16_as_ushort(__float2bfloat16(r));
}

// ---------------- prep kernels ----------------
__global__ void prep_xc(const float* __restrict__ x) {
    int i = blockIdx.x * blockDim.x + threadIdx.x;
    if (i == 0) {
#pragma unroll
        for (int e = 0; e < NEXP; e++) { g_cnt[e] = 0; g_esum[e] = 0.0; }
    }
    float4 v = reinterpret_cast<const float4*>(x)[i];
    unsigned short h0, h1, h2, h3, l0, l1, l2, l3;
    bsplit(v.x, h0, l0); bsplit(v.y, h1, l1);
    bsplit(v.z, h2, l2); bsplit(v.w, h3, l3);
    reinterpret_cast<ushort4*>(g_xh)[i] = make_ushort4(h0, h1, h2, h3);
    reinterpret_cast<ushort4*>(g_xl)[i] = make_ushort4(l0, l1, l2, l3);
}

__global__ void prep_wgu(const float* __restrict__ wg, const float* __restrict__ wu) {
    __shared__ float tg[32][33], tu[32][33];
    int hb = blockIdx.x * 32, db = blockIdx.y * 32;
    int tx = threadIdx.x, ty = threadIdx.y;   // (32, 8)
#pragma unroll
    for (int i = 0; i < 4; i++) {
        int d = db + ty + i * 8;
        tg[ty + i * 8][tx] = wg[(size_t)d * EHDIM + hb + tx];
        tu[ty + i * 8][tx] = wu[(size_t)d * EHDIM + hb + tx];
    }
    __syncthreads();
#pragma unroll
    for (int i = 0; i < 4; i++) {
        int h = hb + ty + i * 8;
        size_t o = (size_t)h * DMODEL + db + tx;
        unsigned short hh, ll;
        bsplit(tg[tx][ty + i * 8], hh, ll);
        g_wgh[o] = hh; g_wgl[o] = ll;
        bsplit(tu[tx][ty + i * 8], hh, ll);
        g_wuh[o] = hh; g_wul[o] = ll;
    }
}

__global__ void prep_wd(const float* __restrict__ wd) {
    __shared__ float t[32][33];
    int db = blockIdx.x * 32, hb = blockIdx.y * 32;
    int tx = threadIdx.x, ty = threadIdx.y;
#pragma unroll
    for (int i = 0; i < 4; i++) {
        t[ty + i * 8][tx] = wd[(size_t)(hb + ty + i * 8) * DMODEL + db + tx];
    }
    __syncthreads();
#pragma unroll
    for (int i = 0; i < 4; i++) {
        size_t o = (size_t)(db + ty + i * 8) * HDIM + hb + tx;
        unsigned short hh, ll;
        bsplit(t[tx][ty + i * 8], hh, ll);
        g_wdh[o] = hh; g_wdl[o] = ll;
    }
}

// sum the two expert partials, bf16-split -> A operand of down GEMM
__global__ void convert_part() {
    int i = blockIdx.x * blockDim.x + threadIdx.x;   // over NTOK*HDIM/4
    float4 a = reinterpret_cast<const float4*>(g_part)[i];
    float4 b = reinterpret_cast<const float4*>(g_part + (size_t)NTOK * HDIM)[i];
    unsigned short h0, h1, h2, h3, l0, l1, l2, l3;
    bsplit(a.x + b.x, h0, l0); bsplit(a.y + b.y, h1, l1);
    bsplit(a.z + b.z, h2, l2); bsplit(a.w + b.w, h3, l3);
    reinterpret_cast<ushort4*>(g_ah)[i] = make_ushort4(h0, h1, h2, h3);
    reinterpret_cast<ushort4*>(g_al)[i] = make_ushort4(l0, l1, l2, l3);
}

// ---------------- router: one warp per token ----------------
__global__ void router_kernel(const float* __restrict__ x,
                              const float* __restrict__ w_router) {
    int warp = (blockIdx.x * blockDim.x + threadIdx.x) >> 5;
    int lane = threadIdx.x & 31;
    if (warp >= NTOK) return;
    int n = warp;

    float acc[NEXP];
#pragma unroll
    for (int e = 0; e < NEXP; e++) acc[e] = 0.f;
    const float* xr = x + (size_t)n * DMODEL;
    for (int d = lane; d < DMODEL; d += 32) {
        float xv = xr[d];
        const float* w = w_router + d * NEXP;
#pragma unroll
        for (int e = 0; e < NEXP; e++) acc[e] += xv * w[e];
    }
#pragma unroll
    for (int off = 16; off > 0; off >>= 1)
#pragma unroll
        for (int e = 0; e < NEXP; e++)
            acc[e] += __shfl_xor_sync(0xFFFFFFFFu, acc[e], off);

    if (lane == 0) {
        float mx = acc[0];
#pragma unroll
        for (int e = 1; e < NEXP; e++) mx = fmaxf(mx, acc[e]);
        float s = 0.f, probs[NEXP];
#pragma unroll
        for (int e = 0; e < NEXP; e++) { probs[e] = expf(acc[e] - mx); s += probs[e]; }
        float inv = 1.f / s;
#pragma unroll
        for (int e = 0; e < NEXP; e++) {
            probs[e] *= inv;
            atomicAdd(&g_esum[e], (double)probs[e]);
        }
        int i1 = 0;
#pragma unroll
        for (int e = 1; e < NEXP; e++) if (probs[e] > probs[i1]) i1 = e;
        int i2 = (i1 == 0) ? 1 : 0;
#pragma unroll
        for (int e = 0; e < NEXP; e++)
            if (e != i1 && probs[e] > probs[i2]) i2 = e;

        float p1 = probs[i1], p2 = probs[i2];
        float rn = 1.f / (p1 + p2 + 1e-10f);
        int pos1 = atomicAdd(&g_cnt[i1], 1);
        g_elist[i1 * NTOK + pos1] = n;                // slot 0
        g_eprob[i1 * NTOK + pos1] = p1 * rn;
        int pos2 = atomicAdd(&g_cnt[i2], 1);
        g_elist[i2 * NTOK + pos2] = n | (1 << 16);    // slot 1
        g_eprob[i2 * NTOK + pos2] = p2 * rn;
    }
}

// ---------------- gate/up split-bf16 GEMM v2 ----------------
// 256 threads = 8 warps (wm 0..3 x wn 0..1). BM=128 tokens, BN=64 h (dual G,U).
// Warp tile 32m x 32n (both G and U) -> 48 mma per 12 ldmatrix.x4 per chunk.
// smem row = [hi 32B (k16) | lo 32B | pad 16B] stride 80B.
// 3-stage cp.async, ONE barrier per iteration.
#define GQS 80
#define GSTG 20480                       // X(128*80=10240) + G(5120) + U(5120)
#define GU_X(s) ((s) * GSTG)
#define GU_G(s) ((s) * GSTG + 10240)
#define GU_U(s) ((s) * GSTG + 15360)
#define GU_META (3 * GSTG)               // 61440
#define GU_DYN  (GU_META + 1664)

__global__ __launch_bounds__(256, 2) void gateup_bf16() {
    extern __shared__ __align__(16) char smem[];
    uint32_t sb = smem_u32(smem);
    float*  sP   = reinterpret_cast<float*>(smem + GU_META);          // 128 floats
    float** sDst = reinterpret_cast<float**>(smem + GU_META + 512);   // 128 ptrs

    const int tid = threadIdx.x;
    const int e = blockIdx.z;
    const int cnt = g_cnt[e];
    const int row0 = blockIdx.x * 128;
    if (row0 >= cnt) return;
    const int h0 = blockIdx.y * 64;

    if (tid < 128) {
        int gr = row0 + tid;
        bool valid = gr < cnt;
        int ent = valid ? g_elist[e * NTOK + gr] : 0;
        int t = ent & 0xFFFF;
        int slot = (ent >> 16) & 1;
        sP[tid] = valid ? g_eprob[e * NTOK + gr] : 0.f;
        sDst[tid] = valid ? (g_part + ((size_t)slot * NTOK + t) * HDIM + h0) : (float*)0;
    }

    // cp.async: every thread does 4 ops/chunk: X rows r and r+64, G row r, U row r
    const int q = tid & 3, hilo = q >> 1, seg = q & 1;
    const int r = tid >> 2;                 // 0..63
    const unsigned short* xsrc0;
    const unsigned short* xsrc1;
    {
        int gr0 = row0 + r;
        int gr1 = row0 + r + 64;
        int e0 = (gr0 < cnt) ? g_elist[e * NTOK + gr0] : 0;
        int e1 = (gr1 < cnt) ? g_elist[e * NTOK + gr1] : 0;
        const unsigned short* base = hilo ? g_xl : g_xh;
        xsrc0 = base + (size_t)(e0 & 0xFFFF) * DMODEL + seg * 8;
        xsrc1 = base + (size_t)(e1 & 0xFFFF) * DMODEL + seg * 8;
    }
    const unsigned short* gsrc;
    const unsigned short* usrc;
    {
        size_t ro = (size_t)(e * HDIM + h0 + r) * DMODEL + seg * 8;
        gsrc = (hilo ? g_wgl : g_wgh) + ro;
        usrc = (hilo ? g_wul : g_wuh) + ro;
    }
    const uint32_t xoff0 = (uint32_t)r * GQS + hilo * 32 + seg * 16;
    const uint32_t xoff1 = (uint32_t)(r + 64) * GQS + hilo * 32 + seg * 16;
    const uint32_t woff  = (uint32_t)r * GQS + hilo * 32 + seg * 16;

    // fragment addressing (verified R6/R10 mapping)
    const int warp = tid >> 5, lane = tid & 31;
    const int wm = warp & 3, wn = warp >> 2;   // wm 0..3, wn 0..1
    const int grp = lane >> 2, tig = lane & 3;
    const uint32_t aLane = (uint32_t)(((lane & 7) + (lane & 8)) * GQS + ((lane & 16) ? 16 : 0));
    const uint32_t bLane = (uint32_t)((((lane & 7) + ((lane & 16) >> 1)) * GQS) + ((lane & 8) ? 16 : 0));
    uint32_t aBase[2], bBase[2];
#pragma unroll
    for (int mt = 0; mt < 2; mt++) aBase[mt] = (uint32_t)(wm * 32 + mt * 16) * GQS + aLane;
#pragma unroll
    for (int bh = 0; bh < 2; bh++) bBase[bh] = (uint32_t)(wn * 32 + bh * 16) * GQS + bLane;

    float accG[2][4][4], accU[2][4][4];   // [mt][bh*2+nt][4]
#pragma unroll
    for (int mt = 0; mt < 2; mt++)
#pragma unroll
        for (int j = 0; j < 4; j++)
#pragma unroll
            for (int k = 0; k < 4; k++) { accG[mt][j][k] = 0.f; accU[mt][j][k] = 0.f; }

    // prologue: stages 0,1
#pragma unroll
    for (int c = 0; c < 2; c++) {
        cp16(sb + GU_X(c) + xoff0, xsrc0 + c * 16);
        cp16(sb + GU_X(c) + xoff1, xsrc1 + c * 16);
        cp16(sb + GU_G(c) + woff, gsrc + c * 16);
        cp16(sb + GU_U(c) + woff, usrc + c * 16);
        CP_COMMIT();
    }

    const int NCH = DMODEL / 16;   // 32
    for (int c = 0; c < NCH; c++) {
        int s = c % 3;
        CP_WAIT1();
        __syncthreads();
        if (c + 2 < NCH) {
            int s2 = (c + 2) % 3;
            int k0 = (c + 2) * 16;
            cp16(sb + GU_X(s2) + xoff0, xsrc0 + k0);
            cp16(sb + GU_X(s2) + xoff1, xsrc1 + k0);
            cp16(sb + GU_G(s2) + woff, gsrc + k0);
            cp16(sb + GU_U(s2) + woff, usrc + k0);
        }
        CP_COMMIT();   // uniform group counting

        uint32_t xb = sb + GU_X(s), gb = sb + GU_G(s), ub = sb + GU_U(s);
        uint32_t ah[2][4], al[2][4];
        ldm4(ah[0], xb + aBase[0]); ldm4(al[0], xb + aBase[0] + 32);
        ldm4(ah[1], xb + aBase[1]); ldm4(al[1], xb + aBase[1] + 32);
        // G fragments then mmas, then U (limits live b registers)
        {
            uint32_t bH[2][4], bL[2][4];
            ldm4(bH[0], gb + bBase[0]); ldm4(bL[0], gb + bBase[0] + 32);
            ldm4(bH[1], gb + bBase[1]); ldm4(bL[1], gb + bBase[1] + 32);
#pragma unroll
            for (int mt = 0; mt < 2; mt++)
#pragma unroll
                for (int bh = 0; bh < 2; bh++)
#pragma unroll
                    for (int nt = 0; nt < 2; nt++) {
                        float* acc = accG[mt][bh * 2 + nt];
                        mma16(acc, ah[mt], bH[bh] + nt * 2);
                        mma16(acc, ah[mt], bL[bh] + nt * 2);
                        mma16(acc, al[mt], bH[bh] + nt * 2);
                    }
        }
        {
            uint32_t bH[2][4], bL[2][4];
            ldm4(bH[0], ub + bBase[0]); ldm4(bL[0], ub + bBase[0] + 32);
            ldm4(bH[1], ub + bBase[1]); ldm4(bL[1], ub + bBase[1] + 32);
#pragma unroll
            for (int mt = 0; mt < 2; mt++)
#pragma unroll
                for (int bh = 0; bh < 2; bh++)
#pragma unroll
                    for (int nt = 0; nt < 2; nt++) {
                        float* acc = accU[mt][bh * 2 + nt];
                        mma16(acc, ah[mt], bH[bh] + nt * 2);
                        mma16(acc, ah[mt], bL[bh] + nt * 2);
                        mma16(acc, al[mt], bH[bh] + nt * 2);
                    }
        }
    }

    // epilogue: p * silu(g) * u
#pragma unroll
    for (int mt = 0; mt < 2; mt++) {
        int r0 = wm * 32 + mt * 16 + grp;
        int r1 = r0 + 8;
        float p0 = sP[r0], p1 = sP[r1];
        float* d0 = sDst[r0];
        float* d1 = sDst[r1];
#pragma unroll
        for (int bh = 0; bh < 2; bh++)
#pragma unroll
            for (int nt = 0; nt < 2; nt++) {
                int co = wn * 32 + bh * 16 + nt * 8 + tig * 2;
                const float* aG = accG[mt][bh * 2 + nt];
                const float* aU = accU[mt][bh * 2 + nt];
                if (d0) {
                    float g0 = aG[0], u0 = aU[0];
                    float g1 = aG[1], u1 = aU[1];
                    float2 v;
                    v.x = p0 * (g0 / (1.f + __expf(-g0))) * u0;
                    v.y = p0 * (g1 / (1.f + __expf(-g1))) * u1;
                    *reinterpret_cast<float2*>(d0 + co) = v;
                }
                if (d1) {
                    float g2 = aG[2], u2 = aU[2];
                    float g3 = aG[3], u3 = aU[3];
                    float2 v;
                    v.x = p1 * (g2 / (1.f + __expf(-g2))) * u2;
                    v.y = p1 * (g3 / (1.f + __expf(-g3))) * u3;
                    *reinterpret_cast<float2*>(d1 + co) = v;
                }
            }
    }
}

// ---------------- down split-bf16 GEMM v2 (pure cp.async) ----------------
// 256 threads = 8 warps (wm4 x wn2). BM=128 tokens, BN=64 d-cols, K=2048.
// A = g_ah/g_al (pre-summed/split), B = g_wdh/g_wdl. Same skeleton as gateup v2.
#define DN_A(s) ((s) * 15360)
#define DN_B(s) ((s) * 15360 + 10240)
#define DN_DYN  (3 * 15360)              // 46080

__global__ __launch_bounds__(256, 2) void down_bf16(float* __restrict__ out) {
    extern __shared__ __align__(16) char smem[];
    uint32_t sb = smem_u32(smem);

    const int tid = threadIdx.x;
    const int row0 = blockIdx.x * 128;
    const int c0 = blockIdx.y * 64;

    const int q = tid & 3, hilo = q >> 1, seg = q & 1;
    const int r = tid >> 2;                 // 0..63
    const unsigned short* abase = hilo ? g_al : g_ah;
    const unsigned short* asrc0 = abase + (size_t)(row0 + r) * HDIM + seg * 8;
    const unsigned short* asrc1 = abase + (size_t)(row0 + r + 64) * HDIM + seg * 8;
    const unsigned short* bsrc =
        (hilo ? g_wdl : g_wdh) + (size_t)(c0 + r) * HDIM + seg * 8;
    const uint32_t aoff0 = (uint32_t)r * GQS + hilo * 32 + seg * 16;
    const uint32_t aoff1 = (uint32_t)(r + 64) * GQS + hilo * 32 + seg * 16;
    const uint32_t boff  = (uint32_t)r * GQS + hilo * 32 + seg * 16;

    const int warp = tid >> 5, lane = tid & 31;
    const int wm = warp & 3, wn = warp >> 2;
    const int grp = lane >> 2, tig = lane & 3;
    const uint32_t aLane = (uint32_t)(((lane & 7) + (lane & 8)) * GQS + ((lane & 16) ? 16 : 0));
    const uint32_t bLane = (uint32_t)((((lane & 7) + ((lane & 16) >> 1)) * GQS) + ((lane & 8) ? 16 : 0));
    uint32_t aBase[2], bBase[2];
#pragma unroll
    for (int mt = 0; mt < 2; mt++) aBase[mt] = (uint32_t)(wm * 32 + mt * 16) * GQS + aLane;
#pragma unroll
    for (int bh = 0; bh < 2; bh++) bBase[bh] = (uint32_t)(wn * 32 + bh * 16) * GQS + bLane;

    float acc[2][4][4];
#pragma unroll
    for (int mt = 0; mt < 2; mt++)
#pragma unroll
        for (int j = 0; j < 4; j++)
#pragma unroll
            for (int k = 0; k < 4; k++) acc[mt][j][k] = 0.f;

#pragma unroll
    for (int c = 0; c < 2; c++) {
        cp16(sb + DN_A(c) + aoff0, asrc0 + c * 16);
        cp16(sb + DN_A(c) + aoff1, asrc1 + c * 16);
        cp16(sb + DN_B(c) + boff,  bsrc + c * 16);
        CP_COMMIT();
    }

    const int NCH = HDIM / 16;   // 128
    for (int c = 0; c < NCH; c++) {
        int s = c % 3;
        CP_WAIT1();
        __syncthreads();
        if (c + 2 < NCH) {
            int s2 = (c + 2) % 3;
            int k0 = (c + 2) * 16;
            cp16(sb + DN_A(s2) + aoff0, asrc0 + k0);
            cp16(sb + DN_A(s2) + aoff1, asrc1 + k0);
            cp16(sb + DN_B(s2) + boff,  bsrc + k0);
        }
        CP_COMMIT();

        uint32_t ab = sb + DN_A(s), bb = sb + DN_B(s);
        uint32_t ah[2][4], al[2][4], bH[2][4], bL[2][4];
        ldm4(ah[0], ab + aBase[0]); ldm4(al[0], ab + aBase[0] + 32);
        ldm4(ah[1], ab + aBase[1]); ldm4(al[1], ab + aBase[1] + 32);
        ldm4(bH[0], bb + bBase[0]); ldm4(bL[0], bb + bBase[0] + 32);
        ldm4(bH[1], bb + bBase[1]); ldm4(bL[1], bb + bBase[1] + 32);

#pragma unroll
        for (int mt = 0; mt < 2; mt++)
#pragma unroll
            for (int bh = 0; bh < 2; bh++)
#pragma unroll
                for (int nt = 0; nt < 2; nt++) {
                    float* a = acc[mt][bh * 2 + nt];
                    mma16(a, ah[mt], bH[bh] + nt * 2);
                    mma16(a, ah[mt], bL[bh] + nt * 2);
                    mma16(a, al[mt], bH[bh] + nt * 2);
                }
    }

    // epilogue
#pragma unroll
    for (int mt = 0; mt < 2; mt++) {
        int r0 = row0 + wm * 32 + mt * 16 + grp;
        int r1 = r0 + 8;
#pragma unroll
        for (int bh = 0; bh < 2; bh++)
#pragma unroll
            for (int nt = 0; nt < 2; nt++) {
                int co = c0 + wn * 32 + bh * 16 + nt * 8 + tig * 2;
                const float* a = acc[mt][bh * 2 + nt];
                *reinterpret_cast<float2*>(out + (size_t)r0 * DMODEL + co) =
                    make_float2(a[0], a[1]);
                *reinterpret_cast<float2*>(out + (size_t)r1 * DMODEL + co) =
                    make_float2(a[2], a[3]);
            }
    }
}

// ---------------- load-balancing loss (fp64) ----------------
__global__ void lbloss_kernel(float* __restrict__ out_scalar) {
    if (threadIdx.x == 0 && blockIdx.x == 0) {
        double lb = 0.0;
#pragma unroll
        for (int e = 0; e < NEXP; e++) {
            double m = g_esum[e] / (double)NTOK;
            lb += m * log(m * (double)NEXP + 1e-10);
        }
        out_scalar[0] = (float)((double)NEXP * lb);
    }
}

// ---------------- launch ----------------
extern "C" void kernel_launch(void* const* d_in, const int* in_sizes, int n_in,
                              void* d_out, int out_size) {
    const float* x        = (const float*)d_in[0];
    const float* w_router = (const float*)d_in[1];
    const float* w_gate   = (const float*)d_in[2];
    const float* w_up     = (const float*)d_in[3];
    const float* w_down   = (const float*)d_in[4];
    float* out = (float*)d_out;

    cudaFuncSetAttribute(gateup_bf16, cudaFuncAttributeMaxDynamicSharedMemorySize, GU_DYN);
    cudaFuncSetAttribute(down_bf16,   cudaFuncAttributeMaxDynamicSharedMemorySize, DN_DYN);

    prep_xc<<<(NTOK * DMODEL / 4) / 256, 256>>>(x);             // also zeroes cnt/esum
    prep_wgu<<<dim3(EHDIM / 32, DMODEL / 32), dim3(32, 8)>>>(w_gate, w_up);
    router_kernel<<<NTOK / 8, 256>>>(x, w_router);
    gateup_bf16<<<dim3(NTOK / 128, HDIM / 64, NEXP), 256, GU_DYN>>>();
    convert_part<<<(NTOK * HDIM / 4) / 256, 256>>>();
    prep_wd<<<dim3(DMODEL / 32, HDIM / 32), dim3(32, 8)>>>(w_down);
    down_bf16<<<dim3(NTOK / 128, DMODEL / 64), 256, DN_DYN>>>(out);
    lbloss_kernel<<<1, 32>>>(out + (out_size - 1));
}